// round 7
// baseline (speedup 1.0000x reference)
#include <cuda_runtime.h>
#include <cuda_bf16.h>
#include <math.h>

// PMSN / S4D:  out[h,l] = Re( sum_n coeff_{h,n} * A_bar_{h,n}^l )
//
// R7: two-kernel split.
//   Kernel 1 (precompute, 1 warp per h, branch-uniform): conjugate-pair
//     reduction (2 active states, coeff doubled); writes per-thread seeds
//     z = coeff * A_bar^t (t=0..127) and per-h params (W=A_bar^128, p, q)
//     to __device__ scratch.
//   Kernel 2 (main, 2048x128 = one full wave): pure FMA + STG. Per thread:
//     1x LDG.128 seed + 2x uniform LDG.128 params, then 32 iterations of
//     two order-2 real recurrences  u_{k+2} = p*u_{k+1} + q*u_k.

#define TPB    128
#define NSTATE 4
#define HMAX   4096

// scratch (allocation-free: __device__ globals)
__device__ float4 g_zseed[HMAX * TPB];   // (z0.r, z0.i, z1.r, z1.i) per (h,t)
__device__ float4 g_params[HMAX * 2];    // per h: {Wr,Wi,p,q} x 2 states

struct __align__(8) cfloat { float r, i; };

__device__ __forceinline__ cfloat cmul(cfloat a, cfloat b) {
    cfloat o;
    o.r = fmaf(a.r, b.r, -a.i * b.i);
    o.i = fmaf(a.r, b.i,  a.i * b.r);
    return o;
}

// exp((a + i b) * m), small non-negative integer m (fp32 Cody-Waite).
__device__ __forceinline__ cfloat cexp_scaled(float a, float b, float m) {
    const float INV2PI = 0.15915494309189535f;
    const float C1     = 6.28125f;                  // exact in fp32
    const float C2     = 1.9353071795864764e-3f;    // 2*pi - C1
    float am = a * m;
    float bm = b * m;
    float k  = rintf(bm * INV2PI);
    float r  = fmaf(-k, C1, bm);
    r        = fmaf(-k, C2, r);
    float s, c;
    sincosf(r, &s, &c);
    float e = expf(am);
    cfloat o; o.r = e * c; o.i = e * s;
    return o;
}

// ---------------- kernel 1: precompute ----------------
__global__ __launch_bounds__(TPB)
void pmsn_pre(const float* __restrict__ log_dt,
              const float* __restrict__ log_A_real,
              const float* __restrict__ A_imag,
              const float* __restrict__ VinvB_real,
              const float* __restrict__ VinvB_imag,
              const float* __restrict__ CV_real,
              const float* __restrict__ CV_imag,
              int H)
{
    const int warp = threadIdx.x >> 5;
    const int lane = threadIdx.x & 31;
    const int h    = blockIdx.x * 4 + warp;
    if (h >= H) return;

    const int base = h * NSTATE;
    const float dt = expf(log_dt[h]);

    float4 zout[4];                         // 4 consecutive t values
#pragma unroll
    for (int j = 0; j < 4; ++j) zout[j] = make_float4(0.f, 0.f, 0.f, 0.f);
    float4 par[2];
    par[0] = make_float4(0.f, 0.f, 0.f, 0.f);
    par[1] = make_float4(0.f, 0.f, 0.f, 0.f);

    int slot = 0;
#pragma unroll
    for (int n = 0; n < NSTATE; ++n) {
        const float Aim = A_imag[base + n];
        if (Aim > 0.0f) {                   // uniform branch (same h per warp)
            const float Are = -expf(log_A_real[base + n]);
            const float a = Are * dt;
            const float b = Aim * dt;

            const cfloat Ab = cexp_scaled(a, b, 1.0f);
            // B_bar = (A_bar - 1) * B / A ; coeff = 2 * C * B_bar (pair-doubled)
            const float Br = VinvB_real[base + n], Bi = VinvB_imag[base + n];
            const float t1r = (Ab.r - 1.0f) * Br - Ab.i * Bi;
            const float t1i = (Ab.r - 1.0f) * Bi + Ab.i * Br;
            const float invA = 1.0f / (Are * Are + Aim * Aim);
            const float Bbr = (t1r * Are + t1i * Aim) * invA;
            const float Bbi = (t1i * Are - t1r * Aim) * invA;
            const float Cr = CV_real[base + n], Ci = CV_imag[base + n];
            cfloat cf;
            cf.r = 2.0f * (Cr * Bbr - Ci * Bbi);
            cf.i = 2.0f * (Cr * Bbi + Ci * Bbr);

            // seeds for t = 4*lane .. 4*lane+3
            cfloat z = cmul(cf, cexp_scaled(a, b, (float)(4 * lane)));
#pragma unroll
            for (int j = 0; j < 4; ++j) {
                if (j > 0) z = cmul(z, Ab);
                if (slot == 0) { zout[j].x = z.r; zout[j].y = z.i; }
                else           { zout[j].z = z.r; zout[j].w = z.i; }
            }

            // per-h recurrence params: W = A_bar^128
            const cfloat W = cexp_scaled(a, b, (float)TPB);
            const float p = 2.0f * W.r;
            const float q = -fmaf(W.r, W.r, W.i * W.i);
            par[slot] = make_float4(W.r, W.i, p, q);
            ++slot;
        }
    }

    const int t0 = 4 * lane;
#pragma unroll
    for (int j = 0; j < 4; ++j)
        g_zseed[h * TPB + t0 + j] = zout[j];
    if (lane == 0) {
        g_params[2 * h + 0] = par[0];
        g_params[2 * h + 1] = par[1];
    }
}

// ---------------- kernel 2: main ----------------
__global__ __launch_bounds__(TPB, 16)
void pmsn_main(float* __restrict__ out, int L)
{
    const int h = blockIdx.x;
    const int t = threadIdx.x;

    const float4 z  = g_zseed[h * TPB + t];
    const float4 pa = g_params[2 * h + 0];      // Wr,Wi,p,q  (state 0)
    const float4 pb = g_params[2 * h + 1];      // Wr,Wi,p,q  (state 1)

    float ua0 = z.x;
    float ub0 = fmaf(z.x, pa.x, -z.y * pa.y);   // Re(z0 * W0)
    float ua1 = z.z;
    float ub1 = fmaf(z.z, pb.x, -z.w * pb.y);   // Re(z1 * W1)
    const float p0 = pa.z, q0 = pa.w;
    const float p1 = pb.z, q1 = pb.w;

    float* rowp = out + (size_t)h * (size_t)L + t;

#pragma unroll 8
    for (int l = t; l < L; l += TPB) {
        *rowp = ua0 + ua1;
        rowp += TPB;
        const float n0 = fmaf(p0, ub0, q0 * ua0);
        ua0 = ub0; ub0 = n0;
        const float n1 = fmaf(p1, ub1, q1 * ua1);
        ua1 = ub1; ub1 = n1;
    }
}

extern "C" void kernel_launch(void* const* d_in, const int* in_sizes, int n_in,
                              void* d_out, int out_size)
{
    const float* log_dt     = (const float*)d_in[0];
    const float* log_A_real = (const float*)d_in[1];
    const float* A_imag     = (const float*)d_in[2];
    const float* VinvB_real = (const float*)d_in[3];
    const float* VinvB_imag = (const float*)d_in[4];
    const float* CV_real    = (const float*)d_in[5];
    const float* CV_imag    = (const float*)d_in[6];

    const int H = in_sizes[0];
    const int L = out_size / H;

    float* out = (float*)d_out;

    pmsn_pre<<<(H + 3) / 4, TPB>>>(log_dt, log_A_real, A_imag,
                                   VinvB_real, VinvB_imag,
                                   CV_real, CV_imag, H);
    pmsn_main<<<H, TPB>>>(out, L);
}

// round 8
// speedup vs baseline: 1.0410x; 1.0410x over previous
#include <cuda_runtime.h>
#include <cuda_bf16.h>
#include <math.h>

// PMSN / S4D:  out[h,l] = Re( sum_n coeff_{h,n} * A_bar_{h,n}^l )
//
// R8: single fused kernel, zero smem / zero sync.
//   - Conjugate-pair reduction: only the 2 states with A_imag>0, coeff x2.
//   - Every thread computes its own seeds with MUFU intrinsics
//     (__sincosf/__expf after fp32 Cody-Waite reduction) -> ~10 instr/cexp.
//   - 4 order-2 real recurrence chains per thread (2 states x l0, l0+1),
//     stride 256, float2 stores, 16 iterations.
//     u_{k+2} = p*u_{k+1} + q*u_k,  p = 2 Re(W), q = -|W|^2, W = A_bar^256.

#define NSTATE 4
#define TPB    128

struct __align__(8) cfloat { float r, i; };

__device__ __forceinline__ cfloat cmul(cfloat a, cfloat b) {
    cfloat o;
    o.r = fmaf(a.r, b.r, -a.i * b.i);
    o.i = fmaf(a.r, b.i,  a.i * b.r);
    return o;
}

// exp((a + i b) * m), m small non-negative integer. Fast MUFU path with
// fp32 Cody-Waite phase reduction to |r| <= pi.
__device__ __forceinline__ cfloat cexp_fast(float a, float b, float m) {
    const float INV2PI = 0.15915494309189535f;
    const float C1     = 6.28125f;                  // exact in fp32
    const float C2     = 1.9353071795864764e-3f;    // 2*pi - C1
    float am = a * m;
    float bm = b * m;
    float k  = rintf(bm * INV2PI);
    float r  = fmaf(-k, C1, bm);
    r        = fmaf(-k, C2, r);
    float s, c;
    __sincosf(r, &s, &c);
    float e = __expf(am);
    cfloat o; o.r = e * c; o.i = e * s;
    return o;
}

__global__ __launch_bounds__(TPB, 12)
void pmsn_kernel(const float* __restrict__ log_dt,
                 const float* __restrict__ log_A_real,
                 const float* __restrict__ A_imag,
                 const float* __restrict__ VinvB_real,
                 const float* __restrict__ VinvB_imag,
                 const float* __restrict__ CV_real,
                 const float* __restrict__ CV_imag,
                 float* __restrict__ out,
                 int L)
{
    const int h    = blockIdx.x;
    const int t    = threadIdx.x;
    const int base = h * NSTATE;

    const float dt = __expf(log_dt[h]);

    // find the two states with positive imaginary part (uniform per block)
    int n0 = 0, n1 = 0, cnt = 0;
#pragma unroll
    for (int n = 0; n < NSTATE; ++n) {
        if (A_imag[base + n] > 0.0f) {
            if (cnt == 0) n0 = n; else n1 = n;
            ++cnt;
        }
    }
    const int act[2] = { n0, n1 };

    // 4 chains: [state s][offset 0/1]
    float p[2], q[2];
    float ua0[2], ub0[2];    // offset 0 (l = 2t + 256k)
    float ua1[2], ub1[2];    // offset 1 (l = 2t+1 + 256k)

    const float l0 = (float)(2 * t);

#pragma unroll
    for (int s = 0; s < 2; ++s) {
        const int idx = base + act[s];
        const float Aim = A_imag[idx];
        const float Are = -__expf(log_A_real[idx]);
        const float a = Are * dt;
        const float b = Aim * dt;

        const cfloat Ab = cexp_fast(a, b, 1.0f);

        // B_bar = (A_bar - 1) * B / A ; coeff = 2 * C * B_bar (pair-doubled)
        const float Br = VinvB_real[idx], Bi = VinvB_imag[idx];
        const float t1r = (Ab.r - 1.0f) * Br - Ab.i * Bi;
        const float t1i = (Ab.r - 1.0f) * Bi + Ab.i * Br;
        const float invA = 1.0f / (Are * Are + Aim * Aim);
        const float Bbr = (t1r * Are + t1i * Aim) * invA;
        const float Bbi = (t1i * Are - t1r * Aim) * invA;
        const float Cr = CV_real[idx], Ci = CV_imag[idx];
        cfloat cf;
        cf.r = 2.0f * (Cr * Bbr - Ci * Bbi);
        cf.i = 2.0f * (Cr * Bbi + Ci * Bbr);

        // seeds at l = 2t and 2t+1
        const cfloat z0 = cmul(cf, cexp_fast(a, b, l0));
        const cfloat z1 = cmul(z0, Ab);

        // recurrence params, W = A_bar^256
        const cfloat W = cexp_fast(a, b, 256.0f);
        p[s] = 2.0f * W.r;
        q[s] = -fmaf(W.r, W.r, W.i * W.i);

        ua0[s] = z0.r;
        ub0[s] = fmaf(z0.r, W.r, -z0.i * W.i);
        ua1[s] = z1.r;
        ub1[s] = fmaf(z1.r, W.r, -z1.i * W.i);
    }

    // ---- main loop: 4 chains, float2 stores, stride 256 ----
    float* rowp = out + (size_t)h * (size_t)L + 2 * t;

#pragma unroll 8
    for (int l = 2 * t; l < L; l += 2 * TPB) {
        if (l + 2 <= L) {
            *reinterpret_cast<float2*>(rowp) =
                make_float2(ua0[0] + ua0[1], ua1[0] + ua1[1]);
        } else {
            rowp[0] = ua0[0] + ua0[1];
        }
        rowp += 2 * TPB;
#pragma unroll
        for (int s = 0; s < 2; ++s) {
            const float x0 = fmaf(p[s], ub0[s], q[s] * ua0[s]);
            ua0[s] = ub0[s]; ub0[s] = x0;
            const float x1 = fmaf(p[s], ub1[s], q[s] * ua1[s]);
            ua1[s] = ub1[s]; ub1[s] = x1;
        }
    }
}

extern "C" void kernel_launch(void* const* d_in, const int* in_sizes, int n_in,
                              void* d_out, int out_size)
{
    const float* log_dt     = (const float*)d_in[0];
    const float* log_A_real = (const float*)d_in[1];
    const float* A_imag     = (const float*)d_in[2];
    const float* VinvB_real = (const float*)d_in[3];
    const float* VinvB_imag = (const float*)d_in[4];
    const float* CV_real    = (const float*)d_in[5];
    const float* CV_imag    = (const float*)d_in[6];

    const int H = in_sizes[0];
    const int L = out_size / H;

    float* out = (float*)d_out;

    pmsn_kernel<<<H, TPB>>>(log_dt, log_A_real, A_imag,
                            VinvB_real, VinvB_imag,
                            CV_real, CV_imag, out, L);
}

// round 9
// speedup vs baseline: 1.3890x; 1.3343x over previous
#include <cuda_runtime.h>
#include <cuda_bf16.h>
#include <math.h>

// PMSN / S4D:  out[h,l] = Re( sum_n coeff_{h,n} * A_bar_{h,n}^l )
//
// R9 = R5 (smem power-table seeding, conjugate-pair reduced, order-2 real
// recurrences) + float2 mainloop: thread t owns l = 2t + 256k, 4 chains
// (2 states x adjacent pair), 16 iterations, STG.64 stores.
//   u_{k+2} = p*u_{k+1} + q*u_k,  p = 2 Re(W), q = -|W|^2,  W = A_bar^256.

#define NSTATE 4
#define ACT    2
#define TPB    128

struct __align__(8) cfloat { float r, i; };

__device__ __forceinline__ cfloat cmul(cfloat a, cfloat b) {
    cfloat o;
    o.r = fmaf(a.r, b.r, -a.i * b.i);
    o.i = fmaf(a.r, b.i,  a.i * b.r);
    return o;
}

// exp((a + i b) * m), small non-negative integer m (fp32 Cody-Waite, accurate sincosf).
__device__ __forceinline__ cfloat cexp_scaled(float a, float b, float m) {
    const float INV2PI = 0.15915494309189535f;
    const float C1     = 6.28125f;                  // exact in fp32
    const float C2     = 1.9353071795864764e-3f;    // 2*pi - C1
    float am = a * m;
    float bm = b * m;
    float k  = rintf(bm * INV2PI);
    float r  = fmaf(-k, C1, bm);
    r        = fmaf(-k, C2, r);
    float s, c;
    sincosf(r, &s, &c);
    float e = expf(am);
    cfloat o; o.r = e * c; o.i = e * s;
    return o;
}

__global__ __launch_bounds__(TPB, 12)
void pmsn_kernel(const float* __restrict__ log_dt,
                 const float* __restrict__ log_A_real,
                 const float* __restrict__ A_imag,
                 const float* __restrict__ VinvB_real,
                 const float* __restrict__ VinvB_imag,
                 const float* __restrict__ CV_real,
                 const float* __restrict__ CV_imag,
                 float* __restrict__ out,
                 int L)
{
    __shared__ cfloat sP32[ACT][8];     // A_bar^(32*j), j=0..7
    __shared__ cfloat sP2[ACT][16];     // A_bar^(2*i),  i=0..15
    __shared__ cfloat sAb[ACT];         // A_bar
    __shared__ cfloat sW[ACT];          // A_bar^256
    __shared__ cfloat sCoeff[ACT];      // 2 * C * B_bar

    const int h   = blockIdx.x;
    const int tid = threadIdx.x;

    // ---- setup: 104 lanes, one transcendental job each ----
    if (tid < 104) {
        int n, kind, sub = 0;           // 0=sP32, 1=sP2, 2=sW, 3=Ab+coeff
        if (tid < 32)       { n = tid >> 3;        kind = 0; sub = tid & 7; }
        else if (tid < 96)  { int t = tid - 32; n = t >> 4; kind = 1; sub = t & 15; }
        else if (tid < 100) { n = tid - 96;        kind = 2; }
        else                { n = tid - 100;       kind = 3; }

        const int base = h * NSTATE;
        const float myIm = A_imag[base + n];

        if (myIm > 0.0f) {
            int slot = 0;
            #pragma unroll
            for (int m = 0; m < NSTATE; ++m)
                if (m < n && A_imag[base + m] > 0.0f) ++slot;

            const int idx = base + n;
            const float dt  = expf(log_dt[h]);
            const float Are = -expf(log_A_real[idx]);
            const float a = Are * dt;
            const float b = myIm * dt;

            if (kind == 0) {
                sP32[slot][sub] = cexp_scaled(a, b, (float)(32 * sub));
            } else if (kind == 1) {
                sP2[slot][sub] = cexp_scaled(a, b, (float)(2 * sub));
            } else if (kind == 2) {
                sW[slot] = cexp_scaled(a, b, 256.0f);
            } else {
                cfloat Ab = cexp_scaled(a, b, 1.0f);
                sAb[slot] = Ab;
                // B_bar = (A_bar - 1) * B / A ; coeff = 2 * C * B_bar
                const float Br = VinvB_real[idx], Bi = VinvB_imag[idx];
                const float t1r = (Ab.r - 1.0f) * Br - Ab.i * Bi;
                const float t1i = (Ab.r - 1.0f) * Bi + Ab.i * Br;
                const float invA = 1.0f / (Are * Are + myIm * myIm);
                const float Bbr = (t1r * Are + t1i * myIm) * invA;
                const float Bbi = (t1i * Are - t1r * myIm) * invA;
                const float Cr = CV_real[idx], Ci = CV_imag[idx];
                cfloat cf;
                cf.r = 2.0f * (Cr * Bbr - Ci * Bbi);
                cf.i = 2.0f * (Cr * Bbi + Ci * Bbr);
                sCoeff[slot] = cf;
            }
        }
    }
    __syncthreads();

    // ---- seeds: z0 = coeff * A_bar^(2*tid), z1 = z0 * A_bar ----
    float ua0[ACT], ub0[ACT], ua1[ACT], ub1[ACT], p[ACT], q[ACT];
    const int i2 = tid & 15;            // 2*tid = 32*j + 2*i
    const int j2 = tid >> 4;

#pragma unroll
    for (int s = 0; s < ACT; ++s) {
        const cfloat z0 = cmul(cmul(sCoeff[s], sP32[s][j2]), sP2[s][i2]);
        const cfloat z1 = cmul(z0, sAb[s]);
        const cfloat W  = sW[s];
        ua0[s] = z0.r;
        ub0[s] = fmaf(z0.r, W.r, -z0.i * W.i);
        ua1[s] = z1.r;
        ub1[s] = fmaf(z1.r, W.r, -z1.i * W.i);
        p[s]   = 2.0f * W.r;
        q[s]   = -fmaf(W.r, W.r, W.i * W.i);
    }

    // ---- main loop: 4 chains, float2 stores, stride 256 ----
    float* rowp = out + (size_t)h * (size_t)L + 2 * tid;

#pragma unroll 8
    for (int l = 2 * tid; l < L; l += 2 * TPB) {
        if (l + 2 <= L) {
            *reinterpret_cast<float2*>(rowp) =
                make_float2(ua0[0] + ua0[1], ua1[0] + ua1[1]);
        } else {
            rowp[0] = ua0[0] + ua0[1];
        }
        rowp += 2 * TPB;
#pragma unroll
        for (int s = 0; s < ACT; ++s) {
            const float x0 = fmaf(p[s], ub0[s], q[s] * ua0[s]);
            ua0[s] = ub0[s]; ub0[s] = x0;
            const float x1 = fmaf(p[s], ub1[s], q[s] * ua1[s]);
            ua1[s] = ub1[s]; ub1[s] = x1;
        }
    }
}

extern "C" void kernel_launch(void* const* d_in, const int* in_sizes, int n_in,
                              void* d_out, int out_size)
{
    const float* log_dt     = (const float*)d_in[0];
    const float* log_A_real = (const float*)d_in[1];
    const float* A_imag     = (const float*)d_in[2];
    const float* VinvB_real = (const float*)d_in[3];
    const float* VinvB_imag = (const float*)d_in[4];
    const float* CV_real    = (const float*)d_in[5];
    const float* CV_imag    = (const float*)d_in[6];

    const int H = in_sizes[0];
    const int L = out_size / H;

    float* out = (float*)d_out;

    pmsn_kernel<<<H, TPB>>>(log_dt, log_A_real, A_imag,
                            VinvB_real, VinvB_imag,
                            CV_real, CV_imag, out, L);
}

// round 10
// speedup vs baseline: 1.4052x; 1.0117x over previous
#include <cuda_runtime.h>
#include <cuda_bf16.h>
#include <math.h>

// PMSN / S4D:  out[h,l] = Re( sum_n coeff_{h,n} * A_bar_{h,n}^l )
//
// R10 = R9 (smem power-table seeding, conjugate-pair reduced, 4 order-2 real
// recurrence chains, float2 stores) with:
//   - MUFU (__sincosf/__expf) table construction: ~12 instr/cexp vs ~150
//     for accurate libm (table phase err ~4e-7 rad -> output ~5e-6 rel).
//   - __launch_bounds__(128,16): occupancy to ~64 warps/SM, single wave.

#define NSTATE 4
#define ACT    2
#define TPB    128

struct __align__(8) cfloat { float r, i; };

__device__ __forceinline__ cfloat cmul(cfloat a, cfloat b) {
    cfloat o;
    o.r = fmaf(a.r, b.r, -a.i * b.i);
    o.i = fmaf(a.r, b.i,  a.i * b.r);
    return o;
}

// exp((a + i b) * m), m small non-negative integer. MUFU path with fp32
// Cody-Waite reduction of the phase to |r| <= pi.
__device__ __forceinline__ cfloat cexp_fast(float a, float b, float m) {
    const float INV2PI = 0.15915494309189535f;
    const float C1     = 6.28125f;                  // exact in fp32
    const float C2     = 1.9353071795864764e-3f;    // 2*pi - C1
    float am = a * m;
    float bm = b * m;
    float k  = rintf(bm * INV2PI);
    float r  = fmaf(-k, C1, bm);
    r        = fmaf(-k, C2, r);
    float s, c;
    __sincosf(r, &s, &c);
    float e = __expf(am);
    cfloat o; o.r = e * c; o.i = e * s;
    return o;
}

__global__ __launch_bounds__(TPB, 16)
void pmsn_kernel(const float* __restrict__ log_dt,
                 const float* __restrict__ log_A_real,
                 const float* __restrict__ A_imag,
                 const float* __restrict__ VinvB_real,
                 const float* __restrict__ VinvB_imag,
                 const float* __restrict__ CV_real,
                 const float* __restrict__ CV_imag,
                 float* __restrict__ out,
                 int L)
{
    __shared__ cfloat sP32[ACT][8];     // A_bar^(32*j), j=0..7
    __shared__ cfloat sP2[ACT][16];     // A_bar^(2*i),  i=0..15
    __shared__ cfloat sAb[ACT];         // A_bar
    __shared__ cfloat sW[ACT];          // A_bar^256
    __shared__ cfloat sCoeff[ACT];      // 2 * C * B_bar

    const int h   = blockIdx.x;
    const int tid = threadIdx.x;

    // ---- setup: 104 lanes, one MUFU cexp job each ----
    if (tid < 104) {
        int n, kind, sub = 0;           // 0=sP32, 1=sP2, 2=sW, 3=Ab+coeff
        if (tid < 32)       { n = tid >> 3;        kind = 0; sub = tid & 7; }
        else if (tid < 96)  { int t = tid - 32; n = t >> 4; kind = 1; sub = t & 15; }
        else if (tid < 100) { n = tid - 96;        kind = 2; }
        else                { n = tid - 100;       kind = 3; }

        const int base = h * NSTATE;
        const float myIm = A_imag[base + n];

        if (myIm > 0.0f) {
            int slot = 0;
            #pragma unroll
            for (int m = 0; m < NSTATE; ++m)
                if (m < n && A_imag[base + m] > 0.0f) ++slot;

            const int idx = base + n;
            const float dt  = __expf(log_dt[h]);
            const float Are = -__expf(log_A_real[idx]);
            const float a = Are * dt;
            const float b = myIm * dt;

            if (kind == 0) {
                sP32[slot][sub] = cexp_fast(a, b, (float)(32 * sub));
            } else if (kind == 1) {
                sP2[slot][sub] = cexp_fast(a, b, (float)(2 * sub));
            } else if (kind == 2) {
                sW[slot] = cexp_fast(a, b, 256.0f);
            } else {
                cfloat Ab = cexp_fast(a, b, 1.0f);
                sAb[slot] = Ab;
                // B_bar = (A_bar - 1) * B / A ; coeff = 2 * C * B_bar
                const float Br = VinvB_real[idx], Bi = VinvB_imag[idx];
                const float t1r = (Ab.r - 1.0f) * Br - Ab.i * Bi;
                const float t1i = (Ab.r - 1.0f) * Bi + Ab.i * Br;
                const float invA = 1.0f / (Are * Are + myIm * myIm);
                const float Bbr = (t1r * Are + t1i * myIm) * invA;
                const float Bbi = (t1i * Are - t1r * myIm) * invA;
                const float Cr = CV_real[idx], Ci = CV_imag[idx];
                cfloat cf;
                cf.r = 2.0f * (Cr * Bbr - Ci * Bbi);
                cf.i = 2.0f * (Cr * Bbi + Ci * Bbr);
                sCoeff[slot] = cf;
            }
        }
    }
    __syncthreads();

    // ---- seeds: z0 = coeff * A_bar^(2*tid), z1 = z0 * A_bar ----
    float ua0[ACT], ub0[ACT], ua1[ACT], ub1[ACT], p[ACT], q[ACT];
    const int i2 = tid & 15;            // 2*tid = 32*j + 2*i
    const int j2 = tid >> 4;

#pragma unroll
    for (int s = 0; s < ACT; ++s) {
        const cfloat z0 = cmul(cmul(sCoeff[s], sP32[s][j2]), sP2[s][i2]);
        const cfloat z1 = cmul(z0, sAb[s]);
        const cfloat W  = sW[s];
        ua0[s] = z0.r;
        ub0[s] = fmaf(z0.r, W.r, -z0.i * W.i);
        ua1[s] = z1.r;
        ub1[s] = fmaf(z1.r, W.r, -z1.i * W.i);
        p[s]   = 2.0f * W.r;
        q[s]   = -fmaf(W.r, W.r, W.i * W.i);
    }

    // ---- main loop: 4 chains, float2 stores, stride 256 ----
    float* rowp = out + (size_t)h * (size_t)L + 2 * tid;

#pragma unroll 8
    for (int l = 2 * tid; l < L; l += 2 * TPB) {
        if (l + 2 <= L) {
            *reinterpret_cast<float2*>(rowp) =
                make_float2(ua0[0] + ua0[1], ua1[0] + ua1[1]);
        } else {
            rowp[0] = ua0[0] + ua0[1];
        }
        rowp += 2 * TPB;
#pragma unroll
        for (int s = 0; s < ACT; ++s) {
            const float x0 = fmaf(p[s], ub0[s], q[s] * ua0[s]);
            ua0[s] = ub0[s]; ub0[s] = x0;
            const float x1 = fmaf(p[s], ub1[s], q[s] * ua1[s]);
            ua1[s] = ub1[s]; ub1[s] = x1;
        }
    }
}

extern "C" void kernel_launch(void* const* d_in, const int* in_sizes, int n_in,
                              void* d_out, int out_size)
{
    const float* log_dt     = (const float*)d_in[0];
    const float* log_A_real = (const float*)d_in[1];
    const float* A_imag     = (const float*)d_in[2];
    const float* VinvB_real = (const float*)d_in[3];
    const float* VinvB_imag = (const float*)d_in[4];
    const float* CV_real    = (const float*)d_in[5];
    const float* CV_imag    = (const float*)d_in[6];

    const int H = in_sizes[0];
    const int L = out_size / H;

    float* out = (float*)d_out;

    pmsn_kernel<<<H, TPB>>>(log_dt, log_A_real, A_imag,
                            VinvB_real, VinvB_imag,
                            CV_real, CV_imag, out, L);
}

// round 12
// speedup vs baseline: 1.4388x; 1.0239x over previous
#include <cuda_runtime.h>
#include <cuda_bf16.h>
#include <math.h>

// PMSN / S4D:  out[h,l] = Re( sum_n coeff_{h,n} * A_bar_{h,n}^l )
//
// R11: STG.128 mainloop, branch-free, 8 independent chains.
//   Thread t owns l = 4t + 512k (k=0..7): 2 active states (conjugate-pair
//   reduced) x 4 adjacent l-offsets, each an order-2 real recurrence
//   u_{k+2} = p*u_{k+1} + q*u_k with W = A_bar^512, p = 2ReW, q = -|W|^2.
//   Seeds via smem power table: 4t = 32*(t>>3) + 4*(t&7).

#define NSTATE 4
#define ACT    2
#define TPB    128
#define STRIDE (4 * TPB)    // 512

struct __align__(8) cfloat { float r, i; };

__device__ __forceinline__ cfloat cmul(cfloat a, cfloat b) {
    cfloat o;
    o.r = fmaf(a.r, b.r, -a.i * b.i);
    o.i = fmaf(a.r, b.i,  a.i * b.r);
    return o;
}

// exp((a + i b) * m), m small non-negative integer. MUFU + fp32 Cody-Waite.
__device__ __forceinline__ cfloat cexp_fast(float a, float b, float m) {
    const float INV2PI = 0.15915494309189535f;
    const float C1     = 6.28125f;                  // exact in fp32
    const float C2     = 1.9353071795864764e-3f;    // 2*pi - C1
    float am = a * m;
    float bm = b * m;
    float k  = rintf(bm * INV2PI);
    float r  = fmaf(-k, C1, bm);
    r        = fmaf(-k, C2, r);
    float s, c;
    __sincosf(r, &s, &c);
    float e = __expf(am);
    cfloat o; o.r = e * c; o.i = e * s;
    return o;
}

__global__ __launch_bounds__(TPB, 16)
void pmsn_kernel(const float* __restrict__ log_dt,
                 const float* __restrict__ log_A_real,
                 const float* __restrict__ A_imag,
                 const float* __restrict__ VinvB_real,
                 const float* __restrict__ VinvB_imag,
                 const float* __restrict__ CV_real,
                 const float* __restrict__ CV_imag,
                 float* __restrict__ out,
                 int L)
{
    __shared__ cfloat sP32[ACT][16];    // A_bar^(32*j), j=0..15
    __shared__ cfloat sP4[ACT][8];      // A_bar^(4*i),  i=0..7
    __shared__ cfloat sAb[ACT];         // A_bar
    __shared__ cfloat sW[ACT];          // A_bar^512
    __shared__ cfloat sCoeff[ACT];      // 2 * C * B_bar

    const int h   = blockIdx.x;
    const int tid = threadIdx.x;

    // ---- setup: 104 lanes, one cexp job each ----
    if (tid < 104) {
        int n, kind, sub = 0;           // 0=sP32, 1=sP4, 2=sW, 3=Ab+coeff
        if (tid < 64)       { n = tid >> 4;        kind = 0; sub = tid & 15; }
        else if (tid < 96)  { int t = tid - 64; n = t >> 3; kind = 1; sub = t & 7; }
        else if (tid < 100) { n = tid - 96;        kind = 2; }
        else                { n = tid - 100;       kind = 3; }

        const int base = h * NSTATE;
        const float myIm = A_imag[base + n];

        if (myIm > 0.0f) {
            int slot = 0;
            #pragma unroll
            for (int m = 0; m < NSTATE; ++m)
                if (m < n && A_imag[base + m] > 0.0f) ++slot;

            const int idx = base + n;
            const float dt  = __expf(log_dt[h]);
            const float Are = -__expf(log_A_real[idx]);
            const float a = Are * dt;
            const float b = myIm * dt;

            if (kind == 0) {
                sP32[slot][sub] = cexp_fast(a, b, (float)(32 * sub));
            } else if (kind == 1) {
                sP4[slot][sub] = cexp_fast(a, b, (float)(4 * sub));
            } else if (kind == 2) {
                sW[slot] = cexp_fast(a, b, (float)STRIDE);
            } else {
                cfloat Ab = cexp_fast(a, b, 1.0f);
                sAb[slot] = Ab;
                // B_bar = (A_bar - 1) * B / A ; coeff = 2 * C * B_bar
                const float Br = VinvB_real[idx], Bi = VinvB_imag[idx];
                const float t1r = (Ab.r - 1.0f) * Br - Ab.i * Bi;
                const float t1i = (Ab.r - 1.0f) * Bi + Ab.i * Br;
                const float invA = 1.0f / (Are * Are + myIm * myIm);
                const float Bbr = (t1r * Are + t1i * myIm) * invA;
                const float Bbi = (t1i * Are - t1r * myIm) * invA;
                const float Cr = CV_real[idx], Ci = CV_imag[idx];
                cfloat cf;
                cf.r = 2.0f * (Cr * Bbr - Ci * Bbi);
                cf.i = 2.0f * (Cr * Bbi + Ci * Bbr);
                sCoeff[slot] = cf;
            }
        }
    }
    __syncthreads();

    // ---- seeds: z = coeff * A_bar^(4*tid + o), o = 0..3 ----
    float ua[ACT][4], ub[ACT][4], p[ACT], q[ACT];
    const int i4 = tid & 7;             // 4*tid = 32*j + 4*i
    const int j4 = tid >> 3;

#pragma unroll
    for (int s = 0; s < ACT; ++s) {
        const cfloat Ab = sAb[s];
        const cfloat W  = sW[s];
        cfloat z = cmul(cmul(sCoeff[s], sP32[s][j4]), sP4[s][i4]);
#pragma unroll
        for (int o = 0; o < 4; ++o) {
            if (o > 0) z = cmul(z, Ab);
            ua[s][o] = z.r;
            ub[s][o] = fmaf(z.r, W.r, -z.i * W.i);
        }
        p[s] = 2.0f * W.r;
        q[s] = -fmaf(W.r, W.r, W.i * W.i);
    }

    // ---- main loop: 8 chains, STG.128, branch-free fast path ----
    float* rowp = out + (size_t)h * (size_t)L + 4 * tid;
    const int niter = L / STRIDE;       // L % 512 == 0 fast path

    if (niter * STRIDE == L) {
#pragma unroll 8
        for (int k = 0; k < niter; ++k) {
            float4 v;
            v.x = ua[0][0] + ua[1][0];
            v.y = ua[0][1] + ua[1][1];
            v.z = ua[0][2] + ua[1][2];
            v.w = ua[0][3] + ua[1][3];
            *reinterpret_cast<float4*>(rowp) = v;
            rowp += STRIDE;
#pragma unroll
            for (int s = 0; s < ACT; ++s)
#pragma unroll
                for (int o = 0; o < 4; ++o) {
                    const float x = fmaf(p[s], ub[s][o], q[s] * ua[s][o]);
                    ua[s][o] = ub[s][o];
                    ub[s][o] = x;
                }
        }
    } else {
        for (int l = 4 * tid; l < L; l += STRIDE) {
            float vv[4];
#pragma unroll
            for (int o = 0; o < 4; ++o) vv[o] = ua[0][o] + ua[1][o];
            if (l + 4 <= L) {
                *reinterpret_cast<float4*>(rowp) =
                    make_float4(vv[0], vv[1], vv[2], vv[3]);
            } else {
                for (int o = 0; o < 4 && l + o < L; ++o) rowp[o] = vv[o];
            }
            rowp += STRIDE;
#pragma unroll
            for (int s = 0; s < ACT; ++s)
#pragma unroll
                for (int o = 0; o < 4; ++o) {
                    const float x = fmaf(p[s], ub[s][o], q[s] * ua[s][o]);
                    ua[s][o] = ub[s][o];
                    ub[s][o] = x;
                }
        }
    }
}

extern "C" void kernel_launch(void* const* d_in, const int* in_sizes, int n_in,
                              void* d_out, int out_size)
{
    const float* log_dt     = (const float*)d_in[0];
    const float* log_A_real = (const float*)d_in[1];
    const float* A_imag     = (const float*)d_in[2];
    const float* VinvB_real = (const float*)d_in[3];
    const float* VinvB_imag = (const float*)d_in[4];
    const float* CV_real    = (const float*)d_in[5];
    const float* CV_imag    = (const float*)d_in[6];

    const int H = in_sizes[0];
    const int L = out_size / H;

    float* out = (float*)d_out;

    pmsn_kernel<<<H, TPB>>>(log_dt, log_A_real, A_imag,
                            VinvB_real, VinvB_imag,
                            CV_real, CV_imag, out, L);
}